// round 4
// baseline (speedup 1.0000x reference)
#include <cuda_runtime.h>
#include <cuda_bf16.h>
#include <math.h>
#include <stdint.h>

#define BB   4
#define CC   256
#define NSP  4096
#define EPSN 2.220446049250313e-16f

// ------------------------- device scratch ------------------------------------
__device__ float g_ymean[BB * CC];
__device__ float g_rnx[BB * NSP];
__device__ float g_rny[BB * NSP];
// [b][n][c'] centered+normalized, tf32-rounded, K-permuted within 32-chunks
__device__ float g_Xt[(size_t)BB * NSP * CC];
__device__ float g_Yt[(size_t)BB * NSP * CC];
__device__ __nv_bfloat16 g_S[(size_t)BB * NSP * NSP];   // 128 MB similarity (bf16)
__device__ float g_maxA[BB * NSP];

// ------------------------- helpers -------------------------------------------
__device__ __forceinline__ float to_tf32(float x) {
    uint32_t u;
    asm("cvt.rna.tf32.f32 %0, %1;" : "=r"(u) : "f"(x));
    return __uint_as_float(u);
}
__device__ __forceinline__ uint32_t pack_bf16x2(float lo, float hi) {
    uint32_t r;
    asm("cvt.rn.bf16x2.f32 %0, %1, %2;" : "=r"(r) : "f"(hi), "f"(lo));
    return r;
}
#define CP_ASYNC16(dst, src) \
    asm volatile("cp.async.ca.shared.global [%0], [%1], 16;" :: "r"(dst), "l"(src))
#define CP_COMMIT() asm volatile("cp.async.commit_group;")
#define CP_WAIT(n)  asm volatile("cp.async.wait_group %0;" :: "n"(n))

__device__ __forceinline__ uint32_t smem_u32(const void* p) {
    uint32_t a;
    asm("{ .reg .u64 t; cvta.to.shared.u64 t, %1; cvt.u32.u64 %0, t; }" : "=r"(a) : "l"(p));
    return a;
}
__device__ __forceinline__ void mma_tf32(float* c, const uint32_t* a, const uint32_t* b) {
    asm volatile(
        "mma.sync.aligned.m16n8k8.row.col.f32.tf32.tf32.f32 "
        "{%0,%1,%2,%3}, {%4,%5,%6,%7}, {%8,%9}, {%0,%1,%2,%3};"
        : "+f"(c[0]), "+f"(c[1]), "+f"(c[2]), "+f"(c[3])
        : "r"(a[0]), "r"(a[1]), "r"(a[2]), "r"(a[3]), "r"(b[0]), "r"(b[1]));
}

// fast exp (FFMA-only)
__device__ __forceinline__ float fexp(float x) {
    x = fmaxf(x, -80.0f);
    float y = x * 1.44269504088896341f;
    float r = rintf(y);
    float t = (y - r) * 0.69314718055994531f;
    float p = fmaf(t, 8.3333333e-3f, 4.1666667e-2f);
    p = fmaf(t, p, 1.6666667e-1f);
    p = fmaf(t, p, 5.0e-1f);
    p = fmaf(t, p, 1.0f);
    p = fmaf(t, p, 1.0f);
    return p * __int_as_float(((int)r + 127) << 23);
}

// ------------------------- 1) per-channel spatial mean of Y ------------------
__global__ void k_mean(const float* __restrict__ Y) {
    int bc = blockIdx.x, tid = threadIdx.x;
    const float* p = Y + (size_t)bc * NSP;
    float s = 0.0f;
#pragma unroll
    for (int j = 0; j < 16; j++) s += p[tid + j * 256];
    __shared__ float red[256];
    red[tid] = s; __syncthreads();
    for (int off = 128; off > 0; off >>= 1) {
        if (tid < off) red[tid] += red[tid + off];
        __syncthreads();
    }
    if (tid == 0) g_ymean[bc] = red[0] * (1.0f / NSP);
}

// ------------------------- 2) per-position inverse L2 norms ------------------
__global__ void k_norm(const float* __restrict__ X, const float* __restrict__ Y) {
    int b = blockIdx.y;
    int n = blockIdx.x * 256 + threadIdx.x;
    __shared__ float sm[CC];
    sm[threadIdx.x] = g_ymean[b * CC + threadIdx.x];
    __syncthreads();
    const float* px = X + (size_t)b * CC * NSP + n;
    const float* py = Y + (size_t)b * CC * NSP + n;
    float sx = 0.0f, sy = 0.0f;
#pragma unroll 8
    for (int c = 0; c < CC; c++) {
        float m = sm[c];
        float xv = px[(size_t)c * NSP] - m;
        float yv = py[(size_t)c * NSP] - m;
        sx = fmaf(xv, xv, sx);
        sy = fmaf(yv, yv, sy);
    }
    g_rnx[b * NSP + n] = 1.0f / (sqrtf(sx) + EPSN);
    g_rny[b * NSP + n] = 1.0f / (sqrtf(sy) + EPSN);
}

// --------- 3) center+normalize+transpose to [n][c], tf32-round, K-permute ----
__global__ void k_writeT(const float* __restrict__ X, const float* __restrict__ Y) {
    __shared__ float tx[32][33], ty[32][33];
    int b = blockIdx.z;
    int c0 = blockIdx.y * 32, n0 = blockIdx.x * 32;
    int lx = threadIdx.x, ly = threadIdx.y;   // 32 x 8
#pragma unroll
    for (int j = 0; j < 4; j++) {
        int c = c0 + ly + j * 8;
        float m = g_ymean[b * CC + c];
        size_t src = ((size_t)(b * CC + c) << 12) + n0 + lx;
        tx[ly + j * 8][lx] = X[src] - m;
        ty[ly + j * 8][lx] = Y[src] - m;
    }
    __syncthreads();
    int c = c0 + lx;
    int cp = (c & ~31) | (((c & 3) << 3) | ((c & 31) >> 2));
#pragma unroll
    for (int j = 0; j < 4; j++) {
        int n = n0 + ly + j * 8;
        size_t dst = ((size_t)((b << 12) + n)) * CC + cp;
        g_Xt[dst] = to_tf32(tx[lx][ly + j * 8] * g_rnx[(b << 12) + n]);
        g_Yt[dst] = to_tf32(ty[lx][ly + j * 8] * g_rny[(b << 12) + n]);
    }
}

// ------------------------- 4) tf32 mma.sync GEMM (3-stage pipeline) ----------
#define TILE_B   16384          // bytes per 128x32 f32 tile
#define NSTAGE   3
#define SMA(st)  ((st) * (2 * TILE_B))
#define SMB(st)  ((st) * (2 * TILE_B) + TILE_B)
#define SM_TOT   (NSTAGE * 2 * TILE_B)   // 96 KB

__global__ void __launch_bounds__(256) k_gemm_mma() {
    extern __shared__ char sm[];
    uint32_t sb = smem_u32(sm);
    int tid = threadIdx.x;
    int l = tid & 31, w = tid >> 5;
    int warpM = w >> 2, warpN = w & 3;
    int b = blockIdx.z;
    int n0 = blockIdx.y * 128, m0 = blockIdx.x * 128;

    const char* Ab = (const char*)(g_Xt + ((size_t)((b << 12) + n0)) * CC);
    const char* Bb = (const char*)(g_Yt + ((size_t)((b << 12) + m0)) * CC);

    int lr = tid >> 3;          // 0..31: row within 32-row pass
    int lc = tid & 7;           // 16B chunk index

    float acc[4][4][4];
#pragma unroll
    for (int i = 0; i < 4; i++)
#pragma unroll
        for (int j = 0; j < 4; j++)
#pragma unroll
            for (int q = 0; q < 4; q++) acc[i][j][q] = 0.0f;

    auto load = [&](int kc, int st) {
#pragma unroll
        for (int it = 0; it < 4; it++) {
            int row = lr + it * 32;
            uint32_t sw = (uint32_t)((lc ^ (row & 7)) << 4);
            CP_ASYNC16(sb + SMA(st) + row * 128 + sw, Ab + (size_t)row * 1024 + kc * 128 + lc * 16);
            CP_ASYNC16(sb + SMB(st) + row * 128 + sw, Bb + (size_t)row * 1024 + kc * 128 + lc * 16);
        }
    };

    load(0, 0); CP_COMMIT();
    load(1, 1); CP_COMMIT();

#pragma unroll
    for (int kc = 0; kc < 8; kc++) {
        int st = kc % NSTAGE;
        CP_WAIT(1);
        __syncthreads();
        if (kc + 2 < 8) load(kc + 2, (kc + 2) % NSTAGE);
        CP_COMMIT();

        // fragment loads: all 4 k-steps at once (K-permuted layout)
        uint32_t Af[4][2][8];   // [mi][row half][k-pos]
        uint32_t Bf[4][8];      // [ni][k-pos]
        int cbase = (l & 3) << 1;
#pragma unroll
        for (int mi = 0; mi < 4; mi++) {
#pragma unroll
            for (int h = 0; h < 2; h++) {
                int r = warpM * 64 + mi * 16 + (l >> 2) + h * 8;
                uint32_t ro = SMA(st) + r * 128;
                *(uint4*)&Af[mi][h][0] = *(const uint4*)(sm + ro + (((cbase)     ^ (r & 7)) << 4));
                *(uint4*)&Af[mi][h][4] = *(const uint4*)(sm + ro + (((cbase + 1) ^ (r & 7)) << 4));
            }
        }
#pragma unroll
        for (int ni = 0; ni < 4; ni++) {
            int r = warpN * 32 + ni * 8 + (l >> 2);
            uint32_t ro = SMB(st) + r * 128;
            *(uint4*)&Bf[ni][0] = *(const uint4*)(sm + ro + (((cbase)     ^ (r & 7)) << 4));
            *(uint4*)&Bf[ni][4] = *(const uint4*)(sm + ro + (((cbase + 1) ^ (r & 7)) << 4));
        }

#pragma unroll
        for (int j = 0; j < 4; j++) {
#pragma unroll
            for (int mi = 0; mi < 4; mi++) {
                uint32_t a[4] = { Af[mi][0][2*j], Af[mi][1][2*j],
                                  Af[mi][0][2*j+1], Af[mi][1][2*j+1] };
#pragma unroll
                for (int ni = 0; ni < 4; ni++) {
                    uint32_t bb[2] = { Bf[ni][2*j], Bf[ni][2*j+1] };
                    mma_tf32(acc[mi][ni], a, bb);
                }
            }
        }
    }

    // --- epilogue: write S as bf16 ---
    __nv_bfloat16* Sp = g_S + (size_t)b * NSP * NSP;
#pragma unroll
    for (int mi = 0; mi < 4; mi++) {
        int r = n0 + warpM * 64 + mi * 16 + (l >> 2);
#pragma unroll
        for (int ni = 0; ni < 4; ni++) {
            int cg = m0 + warpN * 32 + ni * 8 + ((l & 3) << 1);
            *(uint32_t*)(Sp + (size_t)r * NSP + cg)       = pack_bf16x2(acc[mi][ni][0], acc[mi][ni][1]);
            *(uint32_t*)(Sp + (size_t)(r + 8) * NSP + cg) = pack_bf16x2(acc[mi][ni][2], acc[mi][ni][3]);
        }
    }
}

// ------------------------- 5) per-row: smax -> sum_w -> maxA -----------------
__global__ void k_reduce() {
    int row = blockIdx.x, tid = threadIdx.x;
    const uint4* p = (const uint4*)(g_S + (size_t)row * NSP);
    uint4 v0 = p[tid * 2], v1 = p[tid * 2 + 1];
    uint32_t u[8] = { v0.x, v0.y, v0.z, v0.w, v1.x, v1.y, v1.z, v1.w };
    float s[16];
    float mx = -1e30f;
#pragma unroll
    for (int j = 0; j < 8; j++) {
        s[2*j]   = __uint_as_float(u[j] << 16);
        s[2*j+1] = __uint_as_float(u[j] & 0xffff0000u);
        mx = fmaxf(mx, fmaxf(s[2*j], s[2*j+1]));
    }
    __shared__ float red[256];
    red[tid] = mx; __syncthreads();
    for (int off = 128; off > 0; off >>= 1) {
        if (tid < off) red[tid] = fmaxf(red[tid], red[tid + off]);
        __syncthreads();
    }
    float smax = red[0];
    __syncthreads();
    float kk = 10.0f / (1.001f - smax);
    float sum = 0.0f;
#pragma unroll
    for (int j = 0; j < 16; j++) sum += fexp((s[j] - smax + 0.001f) * kk);
    red[tid] = sum; __syncthreads();
    for (int off = 128; off > 0; off >>= 1) {
        if (tid < off) red[tid] += red[tid + off];
        __syncthreads();
    }
    if (tid == 0) g_maxA[row] = fexp(0.001f * kk) / red[0];
}

// ------------------------- 6) loss -------------------------------------------
__global__ void k_final(float* __restrict__ out) {
    int b = blockIdx.x, tid = threadIdx.x;
    float s = 0.0f;
#pragma unroll
    for (int j = 0; j < 16; j++) s += g_maxA[b * NSP + tid + j * 256];
    __shared__ float red[256];
    red[tid] = s; __syncthreads();
    for (int off = 128; off > 0; off >>= 1) {
        if (tid < off) red[tid] += red[tid + off];
        __syncthreads();
    }
    if (tid == 0) out[b] = -logf(red[0] * (1.0f / NSP));
}

// ------------------------- launch --------------------------------------------
extern "C" void kernel_launch(void* const* d_in, const int* in_sizes, int n_in,
                              void* d_out, int out_size) {
    const float* X = (const float*)d_in[0];
    const float* Y = (const float*)d_in[1];
    float* out = (float*)d_out;

    cudaFuncSetAttribute(k_gemm_mma, cudaFuncAttributeMaxDynamicSharedMemorySize, SM_TOT);

    k_mean<<<BB * CC, 256>>>(Y);
    k_norm<<<dim3(NSP / 256, BB), 256>>>(X, Y);
    k_writeT<<<dim3(NSP / 32, CC / 32, BB), dim3(32, 8)>>>(X, Y);
    k_gemm_mma<<<dim3(NSP / 128, NSP / 128, BB), 256, SM_TOT>>>();
    k_reduce<<<BB * NSP, 256>>>();
    k_final<<<BB, 256>>>(out);
}

// round 5
// speedup vs baseline: 1.0343x; 1.0343x over previous
#include <cuda_runtime.h>
#include <cuda_bf16.h>
#include <math.h>
#include <stdint.h>

#define BB   4
#define CC   256
#define NSP  4096
#define EPSN 2.220446049250313e-16f

// ------------------------- device scratch ------------------------------------
__device__ float g_ymean[BB * CC];
__device__ float g_rnx[BB * NSP];
__device__ float g_rny[BB * NSP];
// [b][n][c'] centered+normalized, tf32-rounded, K-permuted within 32-chunks
__device__ float g_Xt[(size_t)BB * NSP * CC];
__device__ float g_Yt[(size_t)BB * NSP * CC];
__device__ __nv_bfloat16 g_S[(size_t)BB * NSP * NSP];   // 128 MB similarity (bf16)
__device__ float g_maxA[BB * NSP];

// ------------------------- helpers -------------------------------------------
__device__ __forceinline__ float to_tf32(float x) {
    uint32_t u;
    asm("cvt.rna.tf32.f32 %0, %1;" : "=r"(u) : "f"(x));
    return __uint_as_float(u);
}
__device__ __forceinline__ uint32_t pack_bf16x2(float lo, float hi) {
    uint32_t r;
    asm("cvt.rn.bf16x2.f32 %0, %1, %2;" : "=r"(r) : "f"(hi), "f"(lo));
    return r;
}
#define CP_ASYNC16(dst, src) \
    asm volatile("cp.async.ca.shared.global [%0], [%1], 16;" :: "r"(dst), "l"(src))
#define CP_COMMIT() asm volatile("cp.async.commit_group;")
#define CP_WAIT(n)  asm volatile("cp.async.wait_group %0;" :: "n"(n))

__device__ __forceinline__ uint32_t smem_u32(const void* p) {
    uint32_t a;
    asm("{ .reg .u64 t; cvta.to.shared.u64 t, %1; cvt.u32.u64 %0, t; }" : "=r"(a) : "l"(p));
    return a;
}
__device__ __forceinline__ void mma_tf32(float* c, const uint32_t* a, const uint32_t* b) {
    asm volatile(
        "mma.sync.aligned.m16n8k8.row.col.f32.tf32.tf32.f32 "
        "{%0,%1,%2,%3}, {%4,%5,%6,%7}, {%8,%9}, {%0,%1,%2,%3};"
        : "+f"(c[0]), "+f"(c[1]), "+f"(c[2]), "+f"(c[3])
        : "r"(a[0]), "r"(a[1]), "r"(a[2]), "r"(a[3]), "r"(b[0]), "r"(b[1]));
}

// fast exp (FFMA-only)
__device__ __forceinline__ float fexp(float x) {
    x = fmaxf(x, -80.0f);
    float y = x * 1.44269504088896341f;
    float r = rintf(y);
    float t = (y - r) * 0.69314718055994531f;
    float p = fmaf(t, 8.3333333e-3f, 4.1666667e-2f);
    p = fmaf(t, p, 1.6666667e-1f);
    p = fmaf(t, p, 5.0e-1f);
    p = fmaf(t, p, 1.0f);
    p = fmaf(t, p, 1.0f);
    return p * __int_as_float(((int)r + 127) << 23);
}

// ------------------------- 1) per-channel spatial mean of Y ------------------
__global__ void k_mean(const float* __restrict__ Y) {
    int bc = blockIdx.x, tid = threadIdx.x;
    const float* p = Y + (size_t)bc * NSP;
    float s = 0.0f;
#pragma unroll
    for (int j = 0; j < 16; j++) s += p[tid + j * 256];
    __shared__ float red[256];
    red[tid] = s; __syncthreads();
    for (int off = 128; off > 0; off >>= 1) {
        if (tid < off) red[tid] += red[tid + off];
        __syncthreads();
    }
    if (tid == 0) g_ymean[bc] = red[0] * (1.0f / NSP);
}

// ------------------------- 2) per-position inverse L2 norms ------------------
__global__ void k_norm(const float* __restrict__ X, const float* __restrict__ Y) {
    int b = blockIdx.y;
    int n = blockIdx.x * 256 + threadIdx.x;
    __shared__ float sm[CC];
    sm[threadIdx.x] = g_ymean[b * CC + threadIdx.x];
    __syncthreads();
    const float* px = X + (size_t)b * CC * NSP + n;
    const float* py = Y + (size_t)b * CC * NSP + n;
    float sx = 0.0f, sy = 0.0f;
#pragma unroll 8
    for (int c = 0; c < CC; c++) {
        float m = sm[c];
        float xv = px[(size_t)c * NSP] - m;
        float yv = py[(size_t)c * NSP] - m;
        sx = fmaf(xv, xv, sx);
        sy = fmaf(yv, yv, sy);
    }
    g_rnx[b * NSP + n] = 1.0f / (sqrtf(sx) + EPSN);
    g_rny[b * NSP + n] = 1.0f / (sqrtf(sy) + EPSN);
}

// --------- 3) center+normalize+transpose to [n][c], tf32-round, K-permute ----
__global__ void k_writeT(const float* __restrict__ X, const float* __restrict__ Y) {
    __shared__ float tx[32][33], ty[32][33];
    int b = blockIdx.z;
    int c0 = blockIdx.y * 32, n0 = blockIdx.x * 32;
    int lx = threadIdx.x, ly = threadIdx.y;   // 32 x 8
#pragma unroll
    for (int j = 0; j < 4; j++) {
        int c = c0 + ly + j * 8;
        float m = g_ymean[b * CC + c];
        size_t src = ((size_t)(b * CC + c) << 12) + n0 + lx;
        tx[ly + j * 8][lx] = X[src] - m;
        ty[ly + j * 8][lx] = Y[src] - m;
    }
    __syncthreads();
    int c = c0 + lx;
    int cp = (c & ~31) | (((c & 3) << 3) | ((c & 31) >> 2));
#pragma unroll
    for (int j = 0; j < 4; j++) {
        int n = n0 + ly + j * 8;
        size_t dst = ((size_t)((b << 12) + n)) * CC + cp;
        g_Xt[dst] = to_tf32(tx[lx][ly + j * 8] * g_rnx[(b << 12) + n]);
        g_Yt[dst] = to_tf32(ty[lx][ly + j * 8] * g_rny[(b << 12) + n]);
    }
}

// ------------------------- 4) tf32 mma.sync GEMM (R3 structure) --------------
// Block 128x128, 8 warps (2m x 4n) of 64x32, BK=32, cp.async double buffer.
#define TILE_B   16384          // bytes per 128x32 f32 tile
#define SMA(st)  ((st) * TILE_B)
#define SMB(st)  (2 * TILE_B + (st) * TILE_B)
#define SM_TOT   (4 * TILE_B)   // 64 KB

__global__ void __launch_bounds__(256, 2) k_gemm_mma() {
    extern __shared__ char sm[];
    uint32_t sb = smem_u32(sm);
    int tid = threadIdx.x;
    int l = tid & 31, w = tid >> 5;
    int warpM = w >> 2, warpN = w & 3;
    int b = blockIdx.z;
    int n0 = blockIdx.y * 128, m0 = blockIdx.x * 128;

    const char* Ab = (const char*)(g_Xt + ((size_t)((b << 12) + n0)) * CC);
    const char* Bb = (const char*)(g_Yt + ((size_t)((b << 12) + m0)) * CC);

    int lr = tid >> 3;          // 0..31: row within 32-row pass
    int lc = tid & 7;           // 16B chunk index

    float acc[4][4][4];
#pragma unroll
    for (int i = 0; i < 4; i++)
#pragma unroll
        for (int j = 0; j < 4; j++)
#pragma unroll
            for (int q = 0; q < 4; q++) acc[i][j][q] = 0.0f;

    auto load = [&](int kc, int st) {
#pragma unroll
        for (int it = 0; it < 4; it++) {
            int row = lr + it * 32;
            uint32_t sw = (uint32_t)((lc ^ (row & 7)) << 4);
            CP_ASYNC16(sb + SMA(st) + row * 128 + sw, Ab + (size_t)row * 1024 + kc * 128 + lc * 16);
            CP_ASYNC16(sb + SMB(st) + row * 128 + sw, Bb + (size_t)row * 1024 + kc * 128 + lc * 16);
        }
    };

    load(0, 0); CP_COMMIT();

    for (int kc = 0; kc < 8; kc++) {
        int st = kc & 1;
        if (kc + 1 < 8) { load(kc + 1, st ^ 1); CP_COMMIT(); }
        if (kc + 1 < 8) { CP_WAIT(1); } else { CP_WAIT(0); }
        __syncthreads();

        // fragment loads: all 4 k-steps at once (K-permuted layout)
        uint32_t Af[4][2][8];   // [mi][row half][k-pos]
        uint32_t Bf[4][8];      // [ni][k-pos]
        int cbase = (l & 3) << 1;
#pragma unroll
        for (int mi = 0; mi < 4; mi++) {
#pragma unroll
            for (int h = 0; h < 2; h++) {
                int r = warpM * 64 + mi * 16 + (l >> 2) + h * 8;
                uint32_t ro = SMA(st) + r * 128;
                *(uint4*)&Af[mi][h][0] = *(const uint4*)(sm + ro + (((cbase)     ^ (r & 7)) << 4));
                *(uint4*)&Af[mi][h][4] = *(const uint4*)(sm + ro + (((cbase + 1) ^ (r & 7)) << 4));
            }
        }
#pragma unroll
        for (int ni = 0; ni < 4; ni++) {
            int r = warpN * 32 + ni * 8 + (l >> 2);
            uint32_t ro = SMB(st) + r * 128;
            *(uint4*)&Bf[ni][0] = *(const uint4*)(sm + ro + (((cbase)     ^ (r & 7)) << 4));
            *(uint4*)&Bf[ni][4] = *(const uint4*)(sm + ro + (((cbase + 1) ^ (r & 7)) << 4));
        }

#pragma unroll
        for (int j = 0; j < 4; j++) {
#pragma unroll
            for (int mi = 0; mi < 4; mi++) {
                uint32_t a[4] = { Af[mi][0][2*j], Af[mi][1][2*j],
                                  Af[mi][0][2*j+1], Af[mi][1][2*j+1] };
#pragma unroll
                for (int ni = 0; ni < 4; ni++) {
                    uint32_t bb[2] = { Bf[ni][2*j], Bf[ni][2*j+1] };
                    mma_tf32(acc[mi][ni], a, bb);
                }
            }
        }
        __syncthreads();
    }

    // --- epilogue: write S as bf16 ---
    __nv_bfloat16* Sp = g_S + (size_t)b * NSP * NSP;
#pragma unroll
    for (int mi = 0; mi < 4; mi++) {
        int r = n0 + warpM * 64 + mi * 16 + (l >> 2);
#pragma unroll
        for (int ni = 0; ni < 4; ni++) {
            int cg = m0 + warpN * 32 + ni * 8 + ((l & 3) << 1);
            *(uint32_t*)(Sp + (size_t)r * NSP + cg)       = pack_bf16x2(acc[mi][ni][0], acc[mi][ni][1]);
            *(uint32_t*)(Sp + (size_t)(r + 8) * NSP + cg) = pack_bf16x2(acc[mi][ni][2], acc[mi][ni][3]);
        }
    }
}

// ------------------------- 5) per-row: smax -> sum_w -> maxA -----------------
__global__ void k_reduce() {
    int row = blockIdx.x, tid = threadIdx.x;
    const uint4* p = (const uint4*)(g_S + (size_t)row * NSP);
    uint4 v0 = p[tid * 2], v1 = p[tid * 2 + 1];
    uint32_t u[8] = { v0.x, v0.y, v0.z, v0.w, v1.x, v1.y, v1.z, v1.w };
    float s[16];
    float mx = -1e30f;
#pragma unroll
    for (int j = 0; j < 8; j++) {
        s[2*j]   = __uint_as_float(u[j] << 16);
        s[2*j+1] = __uint_as_float(u[j] & 0xffff0000u);
        mx = fmaxf(mx, fmaxf(s[2*j], s[2*j+1]));
    }
    __shared__ float red[256];
    red[tid] = mx; __syncthreads();
    for (int off = 128; off > 0; off >>= 1) {
        if (tid < off) red[tid] = fmaxf(red[tid], red[tid + off]);
        __syncthreads();
    }
    float smax = red[0];
    __syncthreads();
    float kk = 10.0f / (1.001f - smax);
    float sum = 0.0f;
#pragma unroll
    for (int j = 0; j < 16; j++) sum += fexp((s[j] - smax + 0.001f) * kk);
    red[tid] = sum; __syncthreads();
    for (int off = 128; off > 0; off >>= 1) {
        if (tid < off) red[tid] += red[tid + off];
        __syncthreads();
    }
    if (tid == 0) g_maxA[row] = fexp(0.001f * kk) / red[0];
}

// ------------------------- 6) loss -------------------------------------------
__global__ void k_final(float* __restrict__ out) {
    int b = blockIdx.x, tid = threadIdx.x;
    float s = 0.0f;
#pragma unroll
    for (int j = 0; j < 16; j++) s += g_maxA[b * NSP + tid + j * 256];
    __shared__ float red[256];
    red[tid] = s; __syncthreads();
    for (int off = 128; off > 0; off >>= 1) {
        if (tid < off) red[tid] += red[tid + off];
        __syncthreads();
    }
    if (tid == 0) out[b] = -logf(red[0] * (1.0f / NSP));
}

// ------------------------- launch --------------------------------------------
extern "C" void kernel_launch(void* const* d_in, const int* in_sizes, int n_in,
                              void* d_out, int out_size) {
    const float* X = (const float*)d_in[0];
    const float* Y = (const float*)d_in[1];
    float* out = (float*)d_out;

    cudaFuncSetAttribute(k_gemm_mma, cudaFuncAttributeMaxDynamicSharedMemorySize, SM_TOT);

    k_mean<<<BB * CC, 256>>>(Y);
    k_norm<<<dim3(NSP / 256, BB), 256>>>(X, Y);
    k_writeT<<<dim3(NSP / 32, CC / 32, BB), dim3(32, 8)>>>(X, Y);
    k_gemm_mma<<<dim3(NSP / 128, NSP / 128, BB), 256, SM_TOT>>>();
    k_reduce<<<BB * NSP, 256>>>();
    k_final<<<BB, 256>>>(out);
}

// round 6
// speedup vs baseline: 1.3684x; 1.3230x over previous
#include <cuda_runtime.h>
#include <cuda_bf16.h>
#include <math.h>
#include <stdint.h>

#define BB   4
#define CC   256
#define NSP  4096
#define EPSN 2.220446049250313e-16f

// ------------------------- device scratch ------------------------------------
__device__ float g_ymean[BB * CC];
__device__ float g_rnx[BB * NSP];
__device__ float g_rny[BB * NSP];
// [b][n][c'] centered+normalized bf16, K-permuted within 32-chunks
__device__ __nv_bfloat16 g_Xt[(size_t)BB * NSP * CC];
__device__ __nv_bfloat16 g_Yt[(size_t)BB * NSP * CC];
__device__ __nv_bfloat16 g_S[(size_t)BB * NSP * NSP];   // 128 MB similarity (bf16)
__device__ float g_maxA[BB * NSP];

// ------------------------- helpers -------------------------------------------
__device__ __forceinline__ uint32_t pack_bf16x2(float lo, float hi) {
    uint32_t r;
    asm("cvt.rn.bf16x2.f32 %0, %1, %2;" : "=r"(r) : "f"(hi), "f"(lo));
    return r;
}
#define CP_ASYNC16(dst, src) \
    asm volatile("cp.async.ca.shared.global [%0], [%1], 16;" :: "r"(dst), "l"(src))
#define CP_COMMIT() asm volatile("cp.async.commit_group;")
#define CP_WAIT(n)  asm volatile("cp.async.wait_group %0;" :: "n"(n))

__device__ __forceinline__ uint32_t smem_u32(const void* p) {
    uint32_t a;
    asm("{ .reg .u64 t; cvta.to.shared.u64 t, %1; cvt.u32.u64 %0, t; }" : "=r"(a) : "l"(p));
    return a;
}
__device__ __forceinline__ void mma_bf16(float* c, uint32_t a0, uint32_t a1,
                                         uint32_t a2, uint32_t a3,
                                         uint32_t b0, uint32_t b1) {
    asm volatile(
        "mma.sync.aligned.m16n8k16.row.col.f32.bf16.bf16.f32 "
        "{%0,%1,%2,%3}, {%4,%5,%6,%7}, {%8,%9}, {%0,%1,%2,%3};"
        : "+f"(c[0]), "+f"(c[1]), "+f"(c[2]), "+f"(c[3])
        : "r"(a0), "r"(a1), "r"(a2), "r"(a3), "r"(b0), "r"(b1));
}

// fast exp (FFMA-only)
__device__ __forceinline__ float fexp(float x) {
    x = fmaxf(x, -80.0f);
    float y = x * 1.44269504088896341f;
    float r = rintf(y);
    float t = (y - r) * 0.69314718055994531f;
    float p = fmaf(t, 8.3333333e-3f, 4.1666667e-2f);
    p = fmaf(t, p, 1.6666667e-1f);
    p = fmaf(t, p, 5.0e-1f);
    p = fmaf(t, p, 1.0f);
    p = fmaf(t, p, 1.0f);
    return p * __int_as_float(((int)r + 127) << 23);
}

// ------------------------- 1) per-channel spatial mean of Y ------------------
__global__ void k_mean(const float* __restrict__ Y) {
    int bc = blockIdx.x, tid = threadIdx.x;
    const float* p = Y + (size_t)bc * NSP;
    float s = 0.0f;
#pragma unroll
    for (int j = 0; j < 16; j++) s += p[tid + j * 256];
    __shared__ float red[256];
    red[tid] = s; __syncthreads();
    for (int off = 128; off > 0; off >>= 1) {
        if (tid < off) red[tid] += red[tid + off];
        __syncthreads();
    }
    if (tid == 0) g_ymean[bc] = red[0] * (1.0f / NSP);
}

// ------------------------- 2) per-position inverse L2 norms ------------------
__global__ void k_norm(const float* __restrict__ X, const float* __restrict__ Y) {
    int b = blockIdx.y;
    int n = blockIdx.x * 256 + threadIdx.x;
    __shared__ float sm[CC];
    sm[threadIdx.x] = g_ymean[b * CC + threadIdx.x];
    __syncthreads();
    const float* px = X + (size_t)b * CC * NSP + n;
    const float* py = Y + (size_t)b * CC * NSP + n;
    float sx = 0.0f, sy = 0.0f;
#pragma unroll 8
    for (int c = 0; c < CC; c++) {
        float m = sm[c];
        float xv = px[(size_t)c * NSP] - m;
        float yv = py[(size_t)c * NSP] - m;
        sx = fmaf(xv, xv, sx);
        sy = fmaf(yv, yv, sy);
    }
    g_rnx[b * NSP + n] = 1.0f / (sqrtf(sx) + EPSN);
    g_rny[b * NSP + n] = 1.0f / (sqrtf(sy) + EPSN);
}

// --------- 3) center+normalize+transpose to [n][c] bf16, K-permute -----------
// Within each 32-wide K-chunk: p = t*8 + c16*4 + h*2 + d, where for k:
// t=(k>>1)&3 (thread-in-group), c16=(k>>4)&1 (16-step), h=(k>>3)&1, d=k&1.
// Then thread t's A/B fragment for BOTH 16-k MMA steps is one 16B LDS.128.
__global__ void k_writeT(const float* __restrict__ X, const float* __restrict__ Y) {
    __shared__ float tx[32][33], ty[32][33];
    int b = blockIdx.z;
    int c0 = blockIdx.y * 32, n0 = blockIdx.x * 32;
    int lx = threadIdx.x, ly = threadIdx.y;   // 32 x 8
#pragma unroll
    for (int j = 0; j < 4; j++) {
        int c = c0 + ly + j * 8;
        float m = g_ymean[b * CC + c];
        size_t src = ((size_t)(b * CC + c) << 12) + n0 + lx;
        tx[ly + j * 8][lx] = X[src] - m;
        ty[ly + j * 8][lx] = Y[src] - m;
    }
    __syncthreads();
    int c = c0 + lx;
    int k = c & 31;
    int p = (((k >> 1) & 3) << 3) | (((k >> 4) & 1) << 2) | (((k >> 3) & 1) << 1) | (k & 1);
    int cp = (c & ~31) | p;
#pragma unroll
    for (int j = 0; j < 4; j++) {
        int n = n0 + ly + j * 8;
        size_t dst = ((size_t)((b << 12) + n)) * CC + cp;
        g_Xt[dst] = __float2bfloat16(tx[lx][ly + j * 8] * g_rnx[(b << 12) + n]);
        g_Yt[dst] = __float2bfloat16(ty[lx][ly + j * 8] * g_rny[(b << 12) + n]);
    }
}

// ------------------------- 4) bf16 mma.sync GEMM -----------------------------
// Block 128x128, 8 warps (2m x 4n) of 64x32, BK=32, cp.async double buffer.
// smem tiles: [128 rows][64 bytes = 32 bf16]; no swizzle needed (64B rows).
#define TILE_B   8192           // bytes per 128x32 bf16 tile
#define SMA(st)  ((st) * TILE_B)
#define SMB(st)  (2 * TILE_B + (st) * TILE_B)
#define SM_TOT   (4 * TILE_B)   // 32 KB

__global__ void __launch_bounds__(256, 2) k_gemm_mma() {
    extern __shared__ char sm[];
    uint32_t sb = smem_u32(sm);
    int tid = threadIdx.x;
    int l = tid & 31, w = tid >> 5;
    int warpM = w >> 2, warpN = w & 3;
    int b = blockIdx.z;
    int n0 = blockIdx.y * 128, m0 = blockIdx.x * 128;

    const char* Ab = (const char*)(g_Xt + ((size_t)((b << 12) + n0)) * CC);
    const char* Bb = (const char*)(g_Yt + ((size_t)((b << 12) + m0)) * CC);

    int lr = tid >> 2;          // 0..63: row within 64-row pass
    int lc4 = tid & 3;          // 16B chunk within 64B row

    float acc[4][4][4];
#pragma unroll
    for (int i = 0; i < 4; i++)
#pragma unroll
        for (int j = 0; j < 4; j++)
#pragma unroll
            for (int q = 0; q < 4; q++) acc[i][j][q] = 0.0f;

    auto load = [&](int kc, int st) {
#pragma unroll
        for (int it = 0; it < 2; it++) {
            int row = lr + it * 64;
            CP_ASYNC16(sb + SMA(st) + row * 64 + lc4 * 16, Ab + (size_t)row * 512 + kc * 64 + lc4 * 16);
            CP_ASYNC16(sb + SMB(st) + row * 64 + lc4 * 16, Bb + (size_t)row * 512 + kc * 64 + lc4 * 16);
        }
    };

    load(0, 0); CP_COMMIT();

    for (int kc = 0; kc < 8; kc++) {
        int st = kc & 1;
        if (kc + 1 < 8) { load(kc + 1, st ^ 1); CP_COMMIT(); }
        if (kc + 1 < 8) { CP_WAIT(1); } else { CP_WAIT(0); }
        __syncthreads();

        // fragment loads: one LDS.128 covers both 16-k MMA steps
        uint4 Af[4][2];     // [mi][row half]
        uint4 Bf[4];        // [ni]
#pragma unroll
        for (int mi = 0; mi < 4; mi++)
#pragma unroll
            for (int h = 0; h < 2; h++) {
                int r = warpM * 64 + mi * 16 + (l >> 2) + h * 8;
                Af[mi][h] = *(const uint4*)(sm + SMA(st) + r * 64 + (l & 3) * 16);
            }
#pragma unroll
        for (int ni = 0; ni < 4; ni++) {
            int r = warpN * 32 + ni * 8 + (l >> 2);
            Bf[ni] = *(const uint4*)(sm + SMB(st) + r * 64 + (l & 3) * 16);
        }

        // k-step 0: .x/.y components; k-step 1: .z/.w
#pragma unroll
        for (int mi = 0; mi < 4; mi++)
#pragma unroll
            for (int ni = 0; ni < 4; ni++)
                mma_bf16(acc[mi][ni], Af[mi][0].x, Af[mi][1].x, Af[mi][0].y, Af[mi][1].y,
                         Bf[ni].x, Bf[ni].y);
#pragma unroll
        for (int mi = 0; mi < 4; mi++)
#pragma unroll
            for (int ni = 0; ni < 4; ni++)
                mma_bf16(acc[mi][ni], Af[mi][0].z, Af[mi][1].z, Af[mi][0].w, Af[mi][1].w,
                         Bf[ni].z, Bf[ni].w);
        __syncthreads();
    }

    // --- epilogue: write S as bf16 ---
    __nv_bfloat16* Sp = g_S + (size_t)b * NSP * NSP;
#pragma unroll
    for (int mi = 0; mi < 4; mi++) {
        int r = n0 + warpM * 64 + mi * 16 + (l >> 2);
#pragma unroll
        for (int ni = 0; ni < 4; ni++) {
            int cg = m0 + warpN * 32 + ni * 8 + ((l & 3) << 1);
            *(uint32_t*)(Sp + (size_t)r * NSP + cg)       = pack_bf16x2(acc[mi][ni][0], acc[mi][ni][1]);
            *(uint32_t*)(Sp + (size_t)(r + 8) * NSP + cg) = pack_bf16x2(acc[mi][ni][2], acc[mi][ni][3]);
        }
    }
}

// ------------------------- 5) per-row: smax -> sum_w -> maxA -----------------
__global__ void k_reduce() {
    int row = blockIdx.x, tid = threadIdx.x;
    const uint4* p = (const uint4*)(g_S + (size_t)row * NSP);
    uint4 v0 = p[tid * 2], v1 = p[tid * 2 + 1];
    uint32_t u[8] = { v0.x, v0.y, v0.z, v0.w, v1.x, v1.y, v1.z, v1.w };
    float s[16];
    float mx = -1e30f;
#pragma unroll
    for (int j = 0; j < 8; j++) {
        s[2*j]   = __uint_as_float(u[j] << 16);
        s[2*j+1] = __uint_as_float(u[j] & 0xffff0000u);
        mx = fmaxf(mx, fmaxf(s[2*j], s[2*j+1]));
    }
    __shared__ float red[256];
    red[tid] = mx; __syncthreads();
    for (int off = 128; off > 0; off >>= 1) {
        if (tid < off) red[tid] = fmaxf(red[tid], red[tid + off]);
        __syncthreads();
    }
    float smax = red[0];
    __syncthreads();
    float kk = 10.0f / (1.001f - smax);
    float sum = 0.0f;
#pragma unroll
    for (int j = 0; j < 16; j++) sum += fexp((s[j] - smax + 0.001f) * kk);
    red[tid] = sum; __syncthreads();
    for (int off = 128; off > 0; off >>= 1) {
        if (tid < off) red[tid] += red[tid + off];
        __syncthreads();
    }
    if (tid == 0) g_maxA[row] = fexp(0.001f * kk) / red[0];
}

// ------------------------- 6) loss -------------------------------------------
__global__ void k_final(float* __restrict__ out) {
    int b = blockIdx.x, tid = threadIdx.x;
    float s = 0.0f;
#pragma unroll
    for (int j = 0; j < 16; j++) s += g_maxA[b * NSP + tid + j * 256];
    __shared__ float red[256];
    red[tid] = s; __syncthreads();
    for (int off = 128; off > 0; off >>= 1) {
        if (tid < off) red[tid] += red[tid + off];
        __syncthreads();
    }
    if (tid == 0) out[b] = -logf(red[0] * (1.0f / NSP));
}

// ------------------------- launch --------------------------------------------
extern "C" void kernel_launch(void* const* d_in, const int* in_sizes, int n_in,
                              void* d_out, int out_size) {
    const float* X = (const float*)d_in[0];
    const float* Y = (const float*)d_in[1];
    float* out = (float*)d_out;

    cudaFuncSetAttribute(k_gemm_mma, cudaFuncAttributeMaxDynamicSharedMemorySize, SM_TOT);

    k_mean<<<BB * CC, 256>>>(Y);
    k_norm<<<dim3(NSP / 256, BB), 256>>>(X, Y);
    k_writeT<<<dim3(NSP / 32, CC / 32, BB), dim3(32, 8)>>>(X, Y);
    k_gemm_mma<<<dim3(NSP / 128, NSP / 128, BB), 256, SM_TOT>>>();
    k_reduce<<<BB * NSP, 256>>>();
    k_final<<<BB, 256>>>(out);
}

// round 7
// speedup vs baseline: 1.4425x; 1.0542x over previous
#include <cuda_runtime.h>
#include <cuda_bf16.h>
#include <math.h>
#include <stdint.h>

#define BB   4
#define CC   256
#define NSP  4096
#define EPSN 2.220446049250313e-16f

// ------------------------- device scratch ------------------------------------
__device__ float g_ymean[BB * CC];
__device__ float g_rnx[BB * NSP];
__device__ float g_rny[BB * NSP];
// [b][n][c'] centered+normalized bf16, K-permuted within 32-chunks
__device__ __nv_bfloat16 g_Xt[(size_t)BB * NSP * CC];
__device__ __nv_bfloat16 g_Yt[(size_t)BB * NSP * CC];
__device__ __nv_bfloat16 g_S[(size_t)BB * NSP * NSP];   // 128 MB similarity (bf16)
__device__ float g_maxA[BB * NSP];

// ------------------------- helpers -------------------------------------------
__device__ __forceinline__ uint32_t pack_bf16x2(float lo, float hi) {
    uint32_t r;
    asm("cvt.rn.bf16x2.f32 %0, %1, %2;" : "=r"(r) : "f"(hi), "f"(lo));
    return r;
}
#define CP_ASYNC16(dst, src) \
    asm volatile("cp.async.ca.shared.global [%0], [%1], 16;" :: "r"(dst), "l"(src))
#define CP_COMMIT() asm volatile("cp.async.commit_group;")
#define CP_WAIT(n)  asm volatile("cp.async.wait_group %0;" :: "n"(n))

__device__ __forceinline__ uint32_t smem_u32(const void* p) {
    uint32_t a;
    asm("{ .reg .u64 t; cvta.to.shared.u64 t, %1; cvt.u32.u64 %0, t; }" : "=r"(a) : "l"(p));
    return a;
}
__device__ __forceinline__ void mma_bf16(float* c, uint32_t a0, uint32_t a1,
                                         uint32_t a2, uint32_t a3,
                                         uint32_t b0, uint32_t b1) {
    asm volatile(
        "mma.sync.aligned.m16n8k16.row.col.f32.bf16.bf16.f32 "
        "{%0,%1,%2,%3}, {%4,%5,%6,%7}, {%8,%9}, {%0,%1,%2,%3};"
        : "+f"(c[0]), "+f"(c[1]), "+f"(c[2]), "+f"(c[3])
        : "r"(a0), "r"(a1), "r"(a2), "r"(a3), "r"(b0), "r"(b1));
}

// fast exp (FFMA-only)
__device__ __forceinline__ float fexp(float x) {
    x = fmaxf(x, -80.0f);
    float y = x * 1.44269504088896341f;
    float r = rintf(y);
    float t = (y - r) * 0.69314718055994531f;
    float p = fmaf(t, 8.3333333e-3f, 4.1666667e-2f);
    p = fmaf(t, p, 1.6666667e-1f);
    p = fmaf(t, p, 5.0e-1f);
    p = fmaf(t, p, 1.0f);
    p = fmaf(t, p, 1.0f);
    return p * __int_as_float(((int)r + 127) << 23);
}

// ------------------------- 1) per-channel spatial mean of Y ------------------
__global__ void k_mean(const float* __restrict__ Y) {
    int bc = blockIdx.x, tid = threadIdx.x;
    const float* p = Y + (size_t)bc * NSP;
    float s = 0.0f;
#pragma unroll
    for (int j = 0; j < 16; j++) s += p[tid + j * 256];
    __shared__ float red[256];
    red[tid] = s; __syncthreads();
    for (int off = 128; off > 0; off >>= 1) {
        if (tid < off) red[tid] += red[tid + off];
        __syncthreads();
    }
    if (tid == 0) g_ymean[bc] = red[0] * (1.0f / NSP);
}

// ------------------------- 2) per-position inverse L2 norms ------------------
__global__ void k_norm(const float* __restrict__ X, const float* __restrict__ Y) {
    int b = blockIdx.y;
    int n = blockIdx.x * 256 + threadIdx.x;
    __shared__ float sm[CC];
    sm[threadIdx.x] = g_ymean[b * CC + threadIdx.x];
    __syncthreads();
    const float* px = X + (size_t)b * CC * NSP + n;
    const float* py = Y + (size_t)b * CC * NSP + n;
    float sx = 0.0f, sy = 0.0f;
#pragma unroll 8
    for (int c = 0; c < CC; c++) {
        float m = sm[c];
        float xv = px[(size_t)c * NSP] - m;
        float yv = py[(size_t)c * NSP] - m;
        sx = fmaf(xv, xv, sx);
        sy = fmaf(yv, yv, sy);
    }
    g_rnx[b * NSP + n] = 1.0f / (sqrtf(sx) + EPSN);
    g_rny[b * NSP + n] = 1.0f / (sqrtf(sy) + EPSN);
}

// --------- 3) center+normalize+transpose to [n][c] bf16, K-permute -----------
__global__ void k_writeT(const float* __restrict__ X, const float* __restrict__ Y) {
    __shared__ float tx[32][33], ty[32][33];
    int b = blockIdx.z;
    int c0 = blockIdx.y * 32, n0 = blockIdx.x * 32;
    int lx = threadIdx.x, ly = threadIdx.y;   // 32 x 8
#pragma unroll
    for (int j = 0; j < 4; j++) {
        int c = c0 + ly + j * 8;
        float m = g_ymean[b * CC + c];
        size_t src = ((size_t)(b * CC + c) << 12) + n0 + lx;
        tx[ly + j * 8][lx] = X[src] - m;
        ty[ly + j * 8][lx] = Y[src] - m;
    }
    __syncthreads();
    int c = c0 + lx;
    int k = c & 31;
    int p = (((k >> 1) & 3) << 3) | (((k >> 4) & 1) << 2) | (((k >> 3) & 1) << 1) | (k & 1);
    int cp = (c & ~31) | p;
#pragma unroll
    for (int j = 0; j < 4; j++) {
        int n = n0 + ly + j * 8;
        size_t dst = ((size_t)((b << 12) + n)) * CC + cp;
        g_Xt[dst] = __float2bfloat16(tx[lx][ly + j * 8] * g_rnx[(b << 12) + n]);
        g_Yt[dst] = __float2bfloat16(ty[lx][ly + j * 8] * g_rny[(b << 12) + n]);
    }
}

// ------------------------- 4) bf16 mma.sync GEMM, BK=64 ----------------------
// Block 128x128, 8 warps (2m x 4n) of 64x32, BK=64, cp.async double buffer.
// smem tiles: [128 rows][128 bytes = 64 bf16]; swizzle: chunk ^= (row&1)*4.
#define TILE_B   16384          // bytes per 128x64 bf16 tile
#define SMA(st)  ((st) * 2 * TILE_B)
#define SMB(st)  ((st) * 2 * TILE_B + TILE_B)
#define SM_TOT   (4 * TILE_B)   // 64 KB

__global__ void __launch_bounds__(256, 2) k_gemm_mma() {
    extern __shared__ char sm[];
    uint32_t sb = smem_u32(sm);
    int tid = threadIdx.x;
    int l = tid & 31, w = tid >> 5;
    int warpM = w >> 2, warpN = w & 3;
    int b = blockIdx.z;
    int n0 = blockIdx.y * 128, m0 = blockIdx.x * 128;

    const char* Ab = (const char*)(g_Xt + ((size_t)((b << 12) + n0)) * CC);
    const char* Bb = (const char*)(g_Yt + ((size_t)((b << 12) + m0)) * CC);

    int lr = tid >> 3;          // 0..31: row within 32-row pass
    int lc = tid & 7;           // 16B chunk within 128B row

    float acc[4][4][4];
#pragma unroll
    for (int i = 0; i < 4; i++)
#pragma unroll
        for (int j = 0; j < 4; j++)
#pragma unroll
            for (int q = 0; q < 4; q++) acc[i][j][q] = 0.0f;

    auto load = [&](int kc, int st) {
#pragma unroll
        for (int it = 0; it < 4; it++) {
            int row = lr + it * 32;
            uint32_t sw = (uint32_t)((lc ^ ((row & 1) << 2)) << 4);
            CP_ASYNC16(sb + SMA(st) + row * 128 + sw, Ab + (size_t)row * 512 + kc * 128 + lc * 16);
            CP_ASYNC16(sb + SMB(st) + row * 128 + sw, Bb + (size_t)row * 512 + kc * 128 + lc * 16);
        }
    };

    load(0, 0); CP_COMMIT();

    for (int kc = 0; kc < 4; kc++) {
        int st = kc & 1;
        if (kc + 1 < 4) { load(kc + 1, st ^ 1); CP_COMMIT(); }
        if (kc + 1 < 4) { CP_WAIT(1); } else { CP_WAIT(0); }
        __syncthreads();

#pragma unroll
        for (int g = 0; g < 2; g++) {
            // fragment loads: one LDS.128 per (frag, group) covers 2 k16 steps
            uint4 Af[4][2];     // [mi][row half]
            uint4 Bf[4];        // [ni]
#pragma unroll
            for (int mi = 0; mi < 4; mi++)
#pragma unroll
                for (int h = 0; h < 2; h++) {
                    int r = warpM * 64 + mi * 16 + (l >> 2) + h * 8;
                    int ch = (g * 4 + (l & 3)) ^ ((r & 1) << 2);
                    Af[mi][h] = *(const uint4*)(sm + SMA(st) + r * 128 + ch * 16);
                }
#pragma unroll
            for (int ni = 0; ni < 4; ni++) {
                int r = warpN * 32 + ni * 8 + (l >> 2);
                int ch = (g * 4 + (l & 3)) ^ ((r & 1) << 2);
                Bf[ni] = *(const uint4*)(sm + SMB(st) + r * 128 + ch * 16);
            }

#pragma unroll
            for (int mi = 0; mi < 4; mi++)
#pragma unroll
                for (int ni = 0; ni < 4; ni++)
                    mma_bf16(acc[mi][ni], Af[mi][0].x, Af[mi][1].x, Af[mi][0].y, Af[mi][1].y,
                             Bf[ni].x, Bf[ni].y);
#pragma unroll
            for (int mi = 0; mi < 4; mi++)
#pragma unroll
                for (int ni = 0; ni < 4; ni++)
                    mma_bf16(acc[mi][ni], Af[mi][0].z, Af[mi][1].z, Af[mi][0].w, Af[mi][1].w,
                             Bf[ni].z, Bf[ni].w);
        }
        __syncthreads();
    }

    // --- epilogue: write S as bf16 ---
    __nv_bfloat16* Sp = g_S + (size_t)b * NSP * NSP;
#pragma unroll
    for (int mi = 0; mi < 4; mi++) {
        int r = n0 + warpM * 64 + mi * 16 + (l >> 2);
#pragma unroll
        for (int ni = 0; ni < 4; ni++) {
            int cg = m0 + warpN * 32 + ni * 8 + ((l & 3) << 1);
            *(uint32_t*)(Sp + (size_t)r * NSP + cg)       = pack_bf16x2(acc[mi][ni][0], acc[mi][ni][1]);
            *(uint32_t*)(Sp + (size_t)(r + 8) * NSP + cg) = pack_bf16x2(acc[mi][ni][2], acc[mi][ni][3]);
        }
    }
}

// ------------------------- 5) per-row: smax -> sum_w -> maxA -----------------
__global__ void k_reduce() {
    int row = blockIdx.x, tid = threadIdx.x;
    const uint4* p = (const uint4*)(g_S + (size_t)row * NSP);
    uint4 v0 = p[tid * 2], v1 = p[tid * 2 + 1];
    uint32_t u[8] = { v0.x, v0.y, v0.z, v0.w, v1.x, v1.y, v1.z, v1.w };
    float s[16];
    float mx = -1e30f;
#pragma unroll
    for (int j = 0; j < 8; j++) {
        s[2*j]   = __uint_as_float(u[j] << 16);
        s[2*j+1] = __uint_as_float(u[j] & 0xffff0000u);
        mx = fmaxf(mx, fmaxf(s[2*j], s[2*j+1]));
    }
    __shared__ float red[256];
    red[tid] = mx; __syncthreads();
    for (int off = 128; off > 0; off >>= 1) {
        if (tid < off) red[tid] = fmaxf(red[tid], red[tid + off]);
        __syncthreads();
    }
    float smax = red[0];
    __syncthreads();
    float kk = 10.0f / (1.001f - smax);
    float sum = 0.0f;
#pragma unroll
    for (int j = 0; j < 16; j++) sum += fexp((s[j] - smax + 0.001f) * kk);
    red[tid] = sum; __syncthreads();
    for (int off = 128; off > 0; off >>= 1) {
        if (tid < off) red[tid] += red[tid + off];
        __syncthreads();
    }
    if (tid == 0) g_maxA[row] = fexp(0.001f * kk) / red[0];
}

// ------------------------- 6) loss -------------------------------------------
__global__ void k_final(float* __restrict__ out) {
    int b = blockIdx.x, tid = threadIdx.x;
    float s = 0.0f;
#pragma unroll
    for (int j = 0; j < 16; j++) s += g_maxA[b * NSP + tid + j * 256];
    __shared__ float red[256];
    red[tid] = s; __syncthreads();
    for (int off = 128; off > 0; off >>= 1) {
        if (tid < off) red[tid] += red[tid + off];
        __syncthreads();
    }
    if (tid == 0) out[b] = -logf(red[0] * (1.0f / NSP));
}

// ------------------------- launch --------------------------------------------
extern "C" void kernel_launch(void* const* d_in, const int* in_sizes, int n_in,
                              void* d_out, int out_size) {
    const float* X = (const float*)d_in[0];
    const float* Y = (const float*)d_in[1];
    float* out = (float*)d_out;

    cudaFuncSetAttribute(k_gemm_mma, cudaFuncAttributeMaxDynamicSharedMemorySize, SM_TOT);

    k_mean<<<BB * CC, 256>>>(Y);
    k_norm<<<dim3(NSP / 256, BB), 256>>>(X, Y);
    k_writeT<<<dim3(NSP / 32, CC / 32, BB), dim3(32, 8)>>>(X, Y);
    k_gemm_mma<<<dim3(NSP / 128, NSP / 128, BB), 256, SM_TOT>>>();
    k_reduce<<<BB * NSP, 256>>>();
    k_final<<<BB, 256>>>(out);
}

// round 8
// speedup vs baseline: 1.5185x; 1.0527x over previous
#include <cuda_runtime.h>
#include <cuda_bf16.h>
#include <math.h>
#include <stdint.h>

#define BB   4
#define CC   256
#define NSP  4096
#define EPSN 2.220446049250313e-16f

// ------------------------- device scratch ------------------------------------
__device__ float g_ymean[BB * CC];
__device__ float g_rnx[BB * NSP];
__device__ float g_rny[BB * NSP];
// [b][n][c'] centered+normalized bf16, K-permuted within 32-chunks
__device__ __nv_bfloat16 g_Xt[(size_t)BB * NSP * CC];
__device__ __nv_bfloat16 g_Yt[(size_t)BB * NSP * CC];
__device__ __nv_bfloat16 g_S[(size_t)BB * NSP * NSP];   // 128 MB similarity (bf16)
__device__ float g_maxA[BB * NSP];

// ------------------------- helpers -------------------------------------------
__device__ __forceinline__ uint32_t pack_bf16x2(float lo, float hi) {
    uint32_t r;
    asm("cvt.rn.bf16x2.f32 %0, %1, %2;" : "=r"(r) : "f"(hi), "f"(lo));
    return r;
}
#define CP_ASYNC16(dst, src) \
    asm volatile("cp.async.ca.shared.global [%0], [%1], 16;" :: "r"(dst), "l"(src))
#define CP_COMMIT() asm volatile("cp.async.commit_group;")
#define CP_WAIT(n)  asm volatile("cp.async.wait_group %0;" :: "n"(n))

__device__ __forceinline__ uint32_t smem_u32(const void* p) {
    uint32_t a;
    asm("{ .reg .u64 t; cvta.to.shared.u64 t, %1; cvt.u32.u64 %0, t; }" : "=r"(a) : "l"(p));
    return a;
}
__device__ __forceinline__ void mma_bf16(float* c, uint32_t a0, uint32_t a1,
                                         uint32_t a2, uint32_t a3,
                                         uint32_t b0, uint32_t b1) {
    asm volatile(
        "mma.sync.aligned.m16n8k16.row.col.f32.bf16.bf16.f32 "
        "{%0,%1,%2,%3}, {%4,%5,%6,%7}, {%8,%9}, {%0,%1,%2,%3};"
        : "+f"(c[0]), "+f"(c[1]), "+f"(c[2]), "+f"(c[3])
        : "r"(a0), "r"(a1), "r"(a2), "r"(a3), "r"(b0), "r"(b1));
}

// fast exp (FFMA-only)
__device__ __forceinline__ float fexp(float x) {
    x = fmaxf(x, -80.0f);
    float y = x * 1.44269504088896341f;
    float r = rintf(y);
    float t = (y - r) * 0.69314718055994531f;
    float p = fmaf(t, 8.3333333e-3f, 4.1666667e-2f);
    p = fmaf(t, p, 1.6666667e-1f);
    p = fmaf(t, p, 5.0e-1f);
    p = fmaf(t, p, 1.0f);
    p = fmaf(t, p, 1.0f);
    return p * __int_as_float(((int)r + 127) << 23);
}

// ------------------------- 1) per-channel spatial mean of Y ------------------
__global__ void k_mean(const float* __restrict__ Y) {
    int bc = blockIdx.x, tid = threadIdx.x;
    const float* p = Y + (size_t)bc * NSP;
    float s = 0.0f;
#pragma unroll
    for (int j = 0; j < 16; j++) s += p[tid + j * 256];
    __shared__ float red[256];
    red[tid] = s; __syncthreads();
    for (int off = 128; off > 0; off >>= 1) {
        if (tid < off) red[tid] += red[tid + off];
        __syncthreads();
    }
    if (tid == 0) g_ymean[bc] = red[0] * (1.0f / NSP);
}

// ------------------------- 2) per-position inverse L2 norms ------------------
__global__ void k_norm(const float* __restrict__ X, const float* __restrict__ Y) {
    int b = blockIdx.y;
    int n = blockIdx.x * 256 + threadIdx.x;
    __shared__ float sm[CC];
    sm[threadIdx.x] = g_ymean[b * CC + threadIdx.x];
    __syncthreads();
    const float* px = X + (size_t)b * CC * NSP + n;
    const float* py = Y + (size_t)b * CC * NSP + n;
    float sx = 0.0f, sy = 0.0f;
#pragma unroll 8
    for (int c = 0; c < CC; c++) {
        float m = sm[c];
        float xv = px[(size_t)c * NSP] - m;
        float yv = py[(size_t)c * NSP] - m;
        sx = fmaf(xv, xv, sx);
        sy = fmaf(yv, yv, sy);
    }
    g_rnx[b * NSP + n] = 1.0f / (sqrtf(sx) + EPSN);
    g_rny[b * NSP + n] = 1.0f / (sqrtf(sy) + EPSN);
}

// --------- 3) center+normalize+transpose to [n][c] bf16, K-permute -----------
__global__ void k_writeT(const float* __restrict__ X, const float* __restrict__ Y) {
    __shared__ float tx[32][33], ty[32][33];
    int b = blockIdx.z;
    int c0 = blockIdx.y * 32, n0 = blockIdx.x * 32;
    int lx = threadIdx.x, ly = threadIdx.y;   // 32 x 8
#pragma unroll
    for (int j = 0; j < 4; j++) {
        int c = c0 + ly + j * 8;
        float m = g_ymean[b * CC + c];
        size_t src = ((size_t)(b * CC + c) << 12) + n0 + lx;
        tx[ly + j * 8][lx] = X[src] - m;
        ty[ly + j * 8][lx] = Y[src] - m;
    }
    __syncthreads();
    int c = c0 + lx;
    int k = c & 31;
    int p = (((k >> 1) & 3) << 3) | (((k >> 4) & 1) << 2) | (((k >> 3) & 1) << 1) | (k & 1);
    int cp = (c & ~31) | p;
#pragma unroll
    for (int j = 0; j < 4; j++) {
        int n = n0 + ly + j * 8;
        size_t dst = ((size_t)((b << 12) + n)) * CC + cp;
        g_Xt[dst] = __float2bfloat16(tx[lx][ly + j * 8] * g_rnx[(b << 12) + n]);
        g_Yt[dst] = __float2bfloat16(ty[lx][ly + j * 8] * g_rny[(b << 12) + n]);
    }
}

// ------------------------- 4) bf16 mma.sync GEMM, BK=64, 1 sync/iter ---------
#define TILE_B   16384          // bytes per 128x64 bf16 tile
#define SMA(st)  ((st) * 2 * TILE_B)
#define SMB(st)  ((st) * 2 * TILE_B + TILE_B)
#define SM_TOT   (4 * TILE_B)   // 64 KB

__global__ void __launch_bounds__(256, 2) k_gemm_mma() {
    extern __shared__ char sm[];
    uint32_t sb = smem_u32(sm);
    int tid = threadIdx.x;
    int l = tid & 31, w = tid >> 5;
    int warpM = w >> 2, warpN = w & 3;
    int b = blockIdx.z;
    int n0 = blockIdx.y * 128, m0 = blockIdx.x * 128;

    const char* Ab = (const char*)(g_Xt + ((size_t)((b << 12) + n0)) * CC);
    const char* Bb = (const char*)(g_Yt + ((size_t)((b << 12) + m0)) * CC);

    int lr = tid >> 3;          // 0..31: row within 32-row pass
    int lc = tid & 7;           // 16B chunk within 128B row

    float acc[4][4][4];
#pragma unroll
    for (int i = 0; i < 4; i++)
#pragma unroll
        for (int j = 0; j < 4; j++)
#pragma unroll
            for (int q = 0; q < 4; q++) acc[i][j][q] = 0.0f;

    auto load = [&](int kc, int st) {
#pragma unroll
        for (int it = 0; it < 4; it++) {
            int row = lr + it * 32;
            uint32_t sw = (uint32_t)((lc ^ ((row & 1) << 2)) << 4);
            CP_ASYNC16(sb + SMA(st) + row * 128 + sw, Ab + (size_t)row * 512 + kc * 128 + lc * 16);
            CP_ASYNC16(sb + SMB(st) + row * 128 + sw, Bb + (size_t)row * 512 + kc * 128 + lc * 16);
        }
    };

    load(0, 0); CP_COMMIT();

    for (int kc = 0; kc < 4; kc++) {
        int st = kc & 1;
        CP_WAIT(0);               // stage st data arrived
        __syncthreads();          // ...and all reads of stage st^1 finished
        if (kc + 1 < 4) { load(kc + 1, st ^ 1); CP_COMMIT(); }

#pragma unroll
        for (int g = 0; g < 2; g++) {
            uint4 Af[4][2];     // [mi][row half]
            uint4 Bf[4];        // [ni]
#pragma unroll
            for (int mi = 0; mi < 4; mi++)
#pragma unroll
                for (int h = 0; h < 2; h++) {
                    int r = warpM * 64 + mi * 16 + (l >> 2) + h * 8;
                    int ch = (g * 4 + (l & 3)) ^ ((r & 1) << 2);
                    Af[mi][h] = *(const uint4*)(sm + SMA(st) + r * 128 + ch * 16);
                }
#pragma unroll
            for (int ni = 0; ni < 4; ni++) {
                int r = warpN * 32 + ni * 8 + (l >> 2);
                int ch = (g * 4 + (l & 3)) ^ ((r & 1) << 2);
                Bf[ni] = *(const uint4*)(sm + SMB(st) + r * 128 + ch * 16);
            }

#pragma unroll
            for (int mi = 0; mi < 4; mi++)
#pragma unroll
                for (int ni = 0; ni < 4; ni++)
                    mma_bf16(acc[mi][ni], Af[mi][0].x, Af[mi][1].x, Af[mi][0].y, Af[mi][1].y,
                             Bf[ni].x, Bf[ni].y);
#pragma unroll
            for (int mi = 0; mi < 4; mi++)
#pragma unroll
                for (int ni = 0; ni < 4; ni++)
                    mma_bf16(acc[mi][ni], Af[mi][0].z, Af[mi][1].z, Af[mi][0].w, Af[mi][1].w,
                             Bf[ni].z, Bf[ni].w);
        }
    }

    // --- epilogue: write S as bf16 ---
    __nv_bfloat16* Sp = g_S + (size_t)b * NSP * NSP;
#pragma unroll
    for (int mi = 0; mi < 4; mi++) {
        int r = n0 + warpM * 64 + mi * 16 + (l >> 2);
#pragma unroll
        for (int ni = 0; ni < 4; ni++) {
            int cg = m0 + warpN * 32 + ni * 8 + ((l & 3) << 1);
            *(uint32_t*)(Sp + (size_t)r * NSP + cg)       = pack_bf16x2(acc[mi][ni][0], acc[mi][ni][1]);
            *(uint32_t*)(Sp + (size_t)(r + 8) * NSP + cg) = pack_bf16x2(acc[mi][ni][2], acc[mi][ni][3]);
        }
    }
}

// ------------------------- 5) per-row: smax -> sum_w -> maxA -----------------
__global__ void k_reduce() {
    int row = blockIdx.x, tid = threadIdx.x;
    int l = tid & 31, w = tid >> 5;
    const uint4* p = (const uint4*)(g_S + (size_t)row * NSP);
    uint4 v0 = p[tid * 2], v1 = p[tid * 2 + 1];
    uint32_t u[8] = { v0.x, v0.y, v0.z, v0.w, v1.x, v1.y, v1.z, v1.w };
    float s[16];
    float mx = -1e30f;
#pragma unroll
    for (int j = 0; j < 8; j++) {
        s[2*j]   = __uint_as_float(u[j] << 16);
        s[2*j+1] = __uint_as_float(u[j] & 0xffff0000u);
        mx = fmaxf(mx, fmaxf(s[2*j], s[2*j+1]));
    }
    __shared__ float red[8];
    __shared__ float bcast;
#pragma unroll
    for (int off = 16; off > 0; off >>= 1)
        mx = fmaxf(mx, __shfl_xor_sync(0xffffffffu, mx, off));
    if (l == 0) red[w] = mx;
    __syncthreads();
    if (tid == 0) {
        float m = red[0];
#pragma unroll
        for (int i = 1; i < 8; i++) m = fmaxf(m, red[i]);
        bcast = m;
    }
    __syncthreads();
    float smax = bcast;
    float kk = 10.0f / (1.001f - smax);
    float sum = 0.0f;
#pragma unroll
    for (int j = 0; j < 16; j++) sum += fexp((s[j] - smax + 0.001f) * kk);
#pragma unroll
    for (int off = 16; off > 0; off >>= 1)
        sum += __shfl_xor_sync(0xffffffffu, sum, off);
    if (l == 0) red[w] = sum;
    __syncthreads();
    if (tid == 0) {
        float t = 0.0f;
#pragma unroll
        for (int i = 0; i < 8; i++) t += red[i];
        g_maxA[row] = fexp(0.001f * kk) / t;
    }
}

// ------------------------- 6) loss -------------------------------------------
__global__ void k_final(float* __restrict__ out) {
    int b = blockIdx.x, tid = threadIdx.x;
    float s = 0.0f;
#pragma unroll
    for (int j = 0; j < 16; j++) s += g_maxA[b * NSP + tid + j * 256];
    __shared__ float red[256];
    red[tid] = s; __syncthreads();
    for (int off = 128; off > 0; off >>= 1) {
        if (tid < off) red[tid] += red[tid + off];
        __syncthreads();
    }
    if (tid == 0) out[b] = -logf(red[0] * (1.0f / NSP));
}

// ------------------------- launch --------------------------------------------
extern "C" void kernel_launch(void* const* d_in, const int* in_sizes, int n_in,
                              void* d_out, int out_size) {
    const float* X = (const float*)d_in[0];
    const float* Y = (const float*)d_in[1];
    float* out = (float*)d_out;

    cudaFuncSetAttribute(k_gemm_mma, cudaFuncAttributeMaxDynamicSharedMemorySize, SM_TOT);

    k_mean<<<BB * CC, 256>>>(Y);
    k_norm<<<dim3(NSP / 256, BB), 256>>>(X, Y);
    k_writeT<<<dim3(NSP / 32, CC / 32, BB), dim3(32, 8)>>>(X, Y);
    k_gemm_mma<<<dim3(NSP / 128, NSP / 128, BB), 256, SM_TOT>>>();
    k_reduce<<<BB * NSP, 256>>>();
    k_final<<<BB, 256>>>(out);
}

// round 9
// speedup vs baseline: 1.7469x; 1.1504x over previous
#include <cuda_runtime.h>
#include <cuda_bf16.h>
#include <math.h>
#include <stdint.h>

#define BB   4
#define CC   256
#define NSP  4096
#define EPSN 2.220446049250313e-16f

// ------------------------- device scratch ------------------------------------
__device__ float g_ymean[BB * CC];
// [b][n][c'] centered+normalized bf16, K-permuted within 32-chunks
__device__ __nv_bfloat16 g_Xt[(size_t)BB * NSP * CC];
__device__ __nv_bfloat16 g_Yt[(size_t)BB * NSP * CC];
__device__ __nv_bfloat16 g_S[(size_t)BB * NSP * NSP];   // 128 MB similarity (bf16)
__device__ float g_maxA[BB * NSP];

// ------------------------- helpers -------------------------------------------
__device__ __forceinline__ uint32_t pack_bf16x2(float lo, float hi) {
    uint32_t r;
    asm("cvt.rn.bf16x2.f32 %0, %1, %2;" : "=r"(r) : "f"(hi), "f"(lo));
    return r;
}
#define CP_ASYNC16(dst, src) \
    asm volatile("cp.async.ca.shared.global [%0], [%1], 16;" :: "r"(dst), "l"(src))
#define CP_COMMIT() asm volatile("cp.async.commit_group;")
#define CP_WAIT(n)  asm volatile("cp.async.wait_group %0;" :: "n"(n))

__device__ __forceinline__ uint32_t smem_u32(const void* p) {
    uint32_t a;
    asm("{ .reg .u64 t; cvta.to.shared.u64 t, %1; cvt.u32.u64 %0, t; }" : "=r"(a) : "l"(p));
    return a;
}
__device__ __forceinline__ void mma_bf16(float* c, uint32_t a0, uint32_t a1,
                                         uint32_t a2, uint32_t a3,
                                         uint32_t b0, uint32_t b1) {
    asm volatile(
        "mma.sync.aligned.m16n8k16.row.col.f32.bf16.bf16.f32 "
        "{%0,%1,%2,%3}, {%4,%5,%6,%7}, {%8,%9}, {%0,%1,%2,%3};"
        : "+f"(c[0]), "+f"(c[1]), "+f"(c[2]), "+f"(c[3])
        : "r"(a0), "r"(a1), "r"(a2), "r"(a3), "r"(b0), "r"(b1));
}

// fast exp (FFMA-only)
__device__ __forceinline__ float fexp(float x) {
    x = fmaxf(x, -80.0f);
    float y = x * 1.44269504088896341f;
    float r = rintf(y);
    float t = (y - r) * 0.69314718055994531f;
    float p = fmaf(t, 8.3333333e-3f, 4.1666667e-2f);
    p = fmaf(t, p, 1.6666667e-1f);
    p = fmaf(t, p, 5.0e-1f);
    p = fmaf(t, p, 1.0f);
    p = fmaf(t, p, 1.0f);
    return p * __int_as_float(((int)r + 127) << 23);
}

// ------------------------- 1) per-channel spatial mean of Y ------------------
__global__ void k_mean(const float* __restrict__ Y) {
    int bc = blockIdx.x, tid = threadIdx.x;
    const float* p = Y + (size_t)bc * NSP;
    float s = 0.0f;
#pragma unroll
    for (int j = 0; j < 16; j++) s += p[tid + j * 256];
    __shared__ float red[256];
    red[tid] = s; __syncthreads();
    for (int off = 128; off > 0; off >>= 1) {
        if (tid < off) red[tid] += red[tid + off];
        __syncthreads();
    }
    if (tid == 0) g_ymean[bc] = red[0] * (1.0f / NSP);
}

// --------- 2) fused: center, norm, transpose to [n][c'] bf16 -----------------
// One block per (b, 32 n-positions). Loads X,Y once, accumulates channel-L2
// norms during load, then writes centered*rnorm as bf16, K-permuted.
#define PREP_SMEM (2 * 256 * 33 * 4)
__global__ void __launch_bounds__(256) k_prep(const float* __restrict__ X,
                                              const float* __restrict__ Y) {
    extern __shared__ float dsm[];
    float* fx = dsm;                 // [256][33]
    float* fy = dsm + 256 * 33;      // [256][33]
    __shared__ float psx[8][32], psy[8][32], rnx_s[32], rny_s[32];

    int b = blockIdx.y;
    int n0 = blockIdx.x * 32;
    int tid = threadIdx.x;
    int n = tid & 31;
    int c8 = tid >> 5;               // 0..7

    float sx = 0.0f, sy = 0.0f;
#pragma unroll 4
    for (int pass = 0; pass < 32; pass++) {
        int c = pass * 8 + c8;
        float m = g_ymean[b * CC + c];
        size_t src = ((size_t)(b * CC + c) << 12) + n0 + n;
        float xv = X[src] - m;
        float yv = Y[src] - m;
        fx[c * 33 + n] = xv;
        fy[c * 33 + n] = yv;
        sx = fmaf(xv, xv, sx);
        sy = fmaf(yv, yv, sy);
    }
    psx[c8][n] = sx;
    psy[c8][n] = sy;
    __syncthreads();
    if (tid < 32) {
        float tx = 0.0f, ty = 0.0f;
#pragma unroll
        for (int i = 0; i < 8; i++) { tx += psx[i][tid]; ty += psy[i][tid]; }
        rnx_s[tid] = 1.0f / (sqrtf(tx) + EPSN);
        rny_s[tid] = 1.0f / (sqrtf(ty) + EPSN);
    }
    __syncthreads();

    int k = tid & 31;
    int p = (((k >> 1) & 3) << 3) | (((k >> 4) & 1) << 2) | (((k >> 3) & 1) << 1) | (k & 1);
#pragma unroll
    for (int pass = 0; pass < 4; pass++) {
        int nn = (tid >> 5) + pass * 8;
        float rx = rnx_s[nn], ry = rny_s[nn];
        size_t base = ((size_t)((b << 12) + n0 + nn)) << 8;
#pragma unroll
        for (int cg = 0; cg < 8; cg++) {
            int c = k + cg * 32;
            int cp = (c & ~31) | p;
            g_Xt[base + cp] = __float2bfloat16(fx[c * 33 + nn] * rx);
            g_Yt[base + cp] = __float2bfloat16(fy[c * 33 + nn] * ry);
        }
    }
}

// ------------------- 3) bf16 mma.sync GEMM, 64x64 warp tiles -----------------
// Block 128x128, 4 warps (2x2) of 64x64, BK=64, double buffer, 1 sync/iter.
#define TILE_B   16384          // bytes per 128x64 bf16 tile
#define SMA(st)  ((st) * 2 * TILE_B)
#define SMB(st)  ((st) * 2 * TILE_B + TILE_B)
#define SM_TOT   (4 * TILE_B)   // 64 KB

__global__ void __launch_bounds__(128, 2) k_gemm_mma() {
    extern __shared__ char sm[];
    uint32_t sb = smem_u32(sm);
    int tid = threadIdx.x;
    int l = tid & 31, w = tid >> 5;
    int warpM = w >> 1, warpN = w & 1;
    int b = blockIdx.z;
    int n0 = blockIdx.y * 128, m0 = blockIdx.x * 128;

    const char* Ab = (const char*)(g_Xt + ((size_t)((b << 12) + n0)) * CC);
    const char* Bb = (const char*)(g_Yt + ((size_t)((b << 12) + m0)) * CC);

    int lr = tid >> 3;          // 0..15: row within 16-row pass
    int lc = tid & 7;           // 16B chunk within 128B row

    float acc[4][8][4];
#pragma unroll
    for (int i = 0; i < 4; i++)
#pragma unroll
        for (int j = 0; j < 8; j++)
#pragma unroll
            for (int q = 0; q < 4; q++) acc[i][j][q] = 0.0f;

    auto load = [&](int kc, int st) {
#pragma unroll
        for (int it = 0; it < 8; it++) {
            int row = lr + it * 16;
            uint32_t sw = (uint32_t)((lc ^ ((row & 1) << 2)) << 4);
            CP_ASYNC16(sb + SMA(st) + row * 128 + sw, Ab + (size_t)row * 512 + kc * 128 + lc * 16);
            CP_ASYNC16(sb + SMB(st) + row * 128 + sw, Bb + (size_t)row * 512 + kc * 128 + lc * 16);
        }
    };

    load(0, 0); CP_COMMIT();

    for (int kc = 0; kc < 4; kc++) {
        int st = kc & 1;
        CP_WAIT(0);               // stage st data arrived
        __syncthreads();          // ...and all reads of stage st^1 finished
        if (kc + 1 < 4) { load(kc + 1, st ^ 1); CP_COMMIT(); }

#pragma unroll
        for (int g = 0; g < 2; g++) {
            uint4 Af[4][2];     // [mi][row half]
            uint4 Bf[8];        // [ni]
#pragma unroll
            for (int mi = 0; mi < 4; mi++)
#pragma unroll
                for (int h = 0; h < 2; h++) {
                    int r = warpM * 64 + mi * 16 + (l >> 2) + h * 8;
                    int ch = (g * 4 + (l & 3)) ^ ((r & 1) << 2);
                    Af[mi][h] = *(const uint4*)(sm + SMA(st) + r * 128 + ch * 16);
                }
#pragma unroll
            for (int ni = 0; ni < 8; ni++) {
                int r = warpN * 64 + ni * 8 + (l >> 2);
                int ch = (g * 4 + (l & 3)) ^ ((r & 1) << 2);
                Bf[ni] = *(const uint4*)(sm + SMB(st) + r * 128 + ch * 16);
            }

#pragma unroll
            for (int mi = 0; mi < 4; mi++)
#pragma unroll
                for (int ni = 0; ni < 8; ni++)
                    mma_bf16(acc[mi][ni], Af[mi][0].x, Af[mi][1].x, Af[mi][0].y, Af[mi][1].y,
                             Bf[ni].x, Bf[ni].y);
#pragma unroll
            for (int mi = 0; mi < 4; mi++)
#pragma unroll
                for (int ni = 0; ni < 8; ni++)
                    mma_bf16(acc[mi][ni], Af[mi][0].z, Af[mi][1].z, Af[mi][0].w, Af[mi][1].w,
                             Bf[ni].z, Bf[ni].w);
        }
    }

    // --- epilogue: write S as bf16 ---
    __nv_bfloat16* Sp = g_S + (size_t)b * NSP * NSP;
#pragma unroll
    for (int mi = 0; mi < 4; mi++) {
        int r = n0 + warpM * 64 + mi * 16 + (l >> 2);
#pragma unroll
        for (int ni = 0; ni < 8; ni++) {
            int cg = m0 + warpN * 64 + ni * 8 + ((l & 3) << 1);
            *(uint32_t*)(Sp + (size_t)r * NSP + cg)       = pack_bf16x2(acc[mi][ni][0], acc[mi][ni][1]);
            *(uint32_t*)(Sp + (size_t)(r + 8) * NSP + cg) = pack_bf16x2(acc[mi][ni][2], acc[mi][ni][3]);
        }
    }
}

// ------------------------- 4) per-row: smax -> sum_w -> maxA -----------------
__global__ void k_reduce() {
    int row = blockIdx.x, tid = threadIdx.x;
    int l = tid & 31, w = tid >> 5;
    const uint4* p = (const uint4*)(g_S + (size_t)row * NSP);
    uint4 v0 = p[tid * 2], v1 = p[tid * 2 + 1];
    uint32_t u[8] = { v0.x, v0.y, v0.z, v0.w, v1.x, v1.y, v1.z, v1.w };
    float s[16];
    float mx = -1e30f;
#pragma unroll
    for (int j = 0; j < 8; j++) {
        s[2*j]   = __uint_as_float(u[j] << 16);
        s[2*j+1] = __uint_as_float(u[j] & 0xffff0000u);
        mx = fmaxf(mx, fmaxf(s[2*j], s[2*j+1]));
    }
    __shared__ float red[8];
    __shared__ float bcast;
#pragma unroll
    for (int off = 16; off > 0; off >>= 1)
        mx = fmaxf(mx, __shfl_xor_sync(0xffffffffu, mx, off));
    if (l == 0) red[w] = mx;
    __syncthreads();
    if (tid == 0) {
        float m = red[0];
#pragma unroll
        for (int i = 1; i < 8; i++) m = fmaxf(m, red[i]);
        bcast = m;
    }
    __syncthreads();
    float smax = bcast;
    float kk = 10.0f / (1.001f - smax);
    float sum = 0.0f;
#pragma unroll
    for (int j = 0; j < 16; j++) sum += fexp((s[j] - smax + 0.001f) * kk);
#pragma unroll
    for (int off = 16; off > 0; off >>= 1)
        sum += __shfl_xor_sync(0xffffffffu, sum, off);
    if (l == 0) red[w] = sum;
    __syncthreads();
    if (tid == 0) {
        float t = 0.0f;
#pragma unroll
        for (int i = 0; i < 8; i++) t += red[i];
        g_maxA[row] = fexp(0.001f * kk) / t;
    }
}

// ------------------------- 5) loss -------------------------------------------
__global__ void k_final(float* __restrict__ out) {
    int b = blockIdx.x, tid = threadIdx.x;
    float s = 0.0f;
#pragma unroll
    for (int j = 0; j < 16; j++) s += g_maxA[b * NSP + tid + j * 256];
    __shared__ float red[256];
    red[tid] = s; __syncthreads();
    for (int off = 128; off > 0; off >>= 1) {
        if (tid < off) red[tid] += red[tid + off];
        __syncthreads();
    }
    if (tid == 0) out[b] = -logf(red[0] * (1.0f / NSP));
}

// ------------------------- launch --------------------------------------------
extern "C" void kernel_launch(void* const* d_in, const int* in_sizes, int n_in,
                              void* d_out, int out_size) {
    const float* X = (const float*)d_in[0];
    const float* Y = (const float*)d_in[1];
    float* out = (float*)d_out;

    cudaFuncSetAttribute(k_prep, cudaFuncAttributeMaxDynamicSharedMemorySize, PREP_SMEM);
    cudaFuncSetAttribute(k_gemm_mma, cudaFuncAttributeMaxDynamicSharedMemorySize, SM_TOT);

    k_mean<<<BB * CC, 256>>>(Y);
    k_prep<<<dim3(NSP / 32, BB), 256, PREP_SMEM>>>(X, Y);
    k_gemm_mma<<<dim3(NSP / 128, NSP / 128, BB), 128, SM_TOT>>>();
    k_reduce<<<BB * NSP, 256>>>();
    k_final<<<BB, 256>>>(out);
}

// round 10
// speedup vs baseline: 1.9215x; 1.0999x over previous
#include <cuda_runtime.h>
#include <cuda_bf16.h>
#include <math.h>
#include <stdint.h>

#define BB   4
#define CC   256
#define NSP  4096
#define EPSN 2.220446049250313e-16f

// ------------------------- device scratch ------------------------------------
__device__ float g_ymean[BB * CC];
// [b][n][c'] centered+normalized bf16, K-permuted within 32-chunks
__device__ __nv_bfloat16 g_Xt[(size_t)BB * NSP * CC];
__device__ __nv_bfloat16 g_Yt[(size_t)BB * NSP * CC];
__device__ __nv_bfloat16 g_S[(size_t)BB * NSP * NSP];   // 128 MB similarity (bf16)
__device__ float g_maxA[BB * NSP];

// ------------------------- helpers -------------------------------------------
__device__ __forceinline__ uint32_t pack_bf16x2(float lo, float hi) {
    uint32_t r;
    asm("cvt.rn.bf16x2.f32 %0, %1, %2;" : "=r"(r) : "f"(hi), "f"(lo));
    return r;
}
#define CP_ASYNC16(dst, src) \
    asm volatile("cp.async.ca.shared.global [%0], [%1], 16;" :: "r"(dst), "l"(src))
#define CP_COMMIT() asm volatile("cp.async.commit_group;")
#define CP_WAIT(n)  asm volatile("cp.async.wait_group %0;" :: "n"(n))

__device__ __forceinline__ uint32_t smem_u32(const void* p) {
    uint32_t a;
    asm("{ .reg .u64 t; cvta.to.shared.u64 t, %1; cvt.u32.u64 %0, t; }" : "=r"(a) : "l"(p));
    return a;
}
__device__ __forceinline__ void mma_bf16(float* c, uint32_t a0, uint32_t a1,
                                         uint32_t a2, uint32_t a3,
                                         uint32_t b0, uint32_t b1) {
    asm volatile(
        "mma.sync.aligned.m16n8k16.row.col.f32.bf16.bf16.f32 "
        "{%0,%1,%2,%3}, {%4,%5,%6,%7}, {%8,%9}, {%0,%1,%2,%3};"
        : "+f"(c[0]), "+f"(c[1]), "+f"(c[2]), "+f"(c[3])
        : "r"(a0), "r"(a1), "r"(a2), "r"(a3), "r"(b0), "r"(b1));
}

// ------------------------- 1) per-channel spatial mean of Y ------------------
__global__ void k_mean(const float* __restrict__ Y) {
    int bc = blockIdx.x, tid = threadIdx.x;
    const float* p = Y + (size_t)bc * NSP;
    float s = 0.0f;
#pragma unroll
    for (int j = 0; j < 16; j++) s += p[tid + j * 256];
    __shared__ float red[256];
    red[tid] = s; __syncthreads();
    for (int off = 128; off > 0; off >>= 1) {
        if (tid < off) red[tid] += red[tid + off];
        __syncthreads();
    }
    if (tid == 0) g_ymean[bc] = red[0] * (1.0f / NSP);
}

// --------- 2) fused: center, norm, transpose to [n][c'] bf16 -----------------
#define PREP_SMEM (2 * 256 * 33 * 4)
__global__ void __launch_bounds__(256) k_prep(const float* __restrict__ X,
                                              const float* __restrict__ Y) {
    extern __shared__ float dsm[];
    float* fx = dsm;                 // [256][33]
    float* fy = dsm + 256 * 33;      // [256][33]
    __shared__ float psx[8][32], psy[8][32], rnx_s[32], rny_s[32];

    int b = blockIdx.y;
    int n0 = blockIdx.x * 32;
    int tid = threadIdx.x;
    int n = tid & 31;
    int c8 = tid >> 5;               // 0..7

    float sx = 0.0f, sy = 0.0f;
#pragma unroll 4
    for (int pass = 0; pass < 32; pass++) {
        int c = pass * 8 + c8;
        float m = g_ymean[b * CC + c];
        size_t src = ((size_t)(b * CC + c) << 12) + n0 + n;
        float xv = X[src] - m;
        float yv = Y[src] - m;
        fx[c * 33 + n] = xv;
        fy[c * 33 + n] = yv;
        sx = fmaf(xv, xv, sx);
        sy = fmaf(yv, yv, sy);
    }
    psx[c8][n] = sx;
    psy[c8][n] = sy;
    __syncthreads();
    if (tid < 32) {
        float tx = 0.0f, ty = 0.0f;
#pragma unroll
        for (int i = 0; i < 8; i++) { tx += psx[i][tid]; ty += psy[i][tid]; }
        rnx_s[tid] = 1.0f / (sqrtf(tx) + EPSN);
        rny_s[tid] = 1.0f / (sqrtf(ty) + EPSN);
    }
    __syncthreads();

    int k = tid & 31;
    int p = (((k >> 1) & 3) << 3) | (((k >> 4) & 1) << 2) | (((k >> 3) & 1) << 1) | (k & 1);
#pragma unroll
    for (int pass = 0; pass < 4; pass++) {
        int nn = (tid >> 5) + pass * 8;
        float rx = rnx_s[nn], ry = rny_s[nn];
        size_t base = ((size_t)((b << 12) + n0 + nn)) << 8;
#pragma unroll
        for (int cg = 0; cg < 8; cg++) {
            int c = k + cg * 32;
            int cp = (c & ~31) | p;
            g_Xt[base + cp] = __float2bfloat16(fx[c * 33 + nn] * rx);
            g_Yt[base + cp] = __float2bfloat16(fy[c * 33 + nn] * ry);
        }
    }
}

// ------------------- 3) bf16 mma.sync GEMM, 64x64 warp tiles -----------------
#define TILE_B   16384          // bytes per 128x64 bf16 tile
#define SMA(st)  ((st) * 2 * TILE_B)
#define SMB(st)  ((st) * 2 * TILE_B + TILE_B)
#define SM_TOT   (4 * TILE_B)   // 64 KB

__global__ void __launch_bounds__(128, 2) k_gemm_mma() {
    extern __shared__ char sm[];
    uint32_t sb = smem_u32(sm);
    int tid = threadIdx.x;
    int l = tid & 31, w = tid >> 5;
    int warpM = w >> 1, warpN = w & 1;
    int b = blockIdx.z;
    int n0 = blockIdx.y * 128, m0 = blockIdx.x * 128;

    const char* Ab = (const char*)(g_Xt + ((size_t)((b << 12) + n0)) * CC);
    const char* Bb = (const char*)(g_Yt + ((size_t)((b << 12) + m0)) * CC);

    int lr = tid >> 3;          // 0..15: row within 16-row pass
    int lc = tid & 7;           // 16B chunk within 128B row

    float acc[4][8][4];
#pragma unroll
    for (int i = 0; i < 4; i++)
#pragma unroll
        for (int j = 0; j < 8; j++)
#pragma unroll
            for (int q = 0; q < 4; q++) acc[i][j][q] = 0.0f;

    auto load = [&](int kc, int st) {
#pragma unroll
        for (int it = 0; it < 8; it++) {
            int row = lr + it * 16;
            uint32_t sw = (uint32_t)((lc ^ ((row & 1) << 2)) << 4);
            CP_ASYNC16(sb + SMA(st) + row * 128 + sw, Ab + (size_t)row * 512 + kc * 128 + lc * 16);
            CP_ASYNC16(sb + SMB(st) + row * 128 + sw, Bb + (size_t)row * 512 + kc * 128 + lc * 16);
        }
    };

    load(0, 0); CP_COMMIT();

    for (int kc = 0; kc < 4; kc++) {
        int st = kc & 1;
        CP_WAIT(0);
        __syncthreads();
        if (kc + 1 < 4) { load(kc + 1, st ^ 1); CP_COMMIT(); }

#pragma unroll
        for (int g = 0; g < 2; g++) {
            uint4 Af[4][2];
            uint4 Bf[8];
#pragma unroll
            for (int mi = 0; mi < 4; mi++)
#pragma unroll
                for (int h = 0; h < 2; h++) {
                    int r = warpM * 64 + mi * 16 + (l >> 2) + h * 8;
                    int ch = (g * 4 + (l & 3)) ^ ((r & 1) << 2);
                    Af[mi][h] = *(const uint4*)(sm + SMA(st) + r * 128 + ch * 16);
                }
#pragma unroll
            for (int ni = 0; ni < 8; ni++) {
                int r = warpN * 64 + ni * 8 + (l >> 2);
                int ch = (g * 4 + (l & 3)) ^ ((r & 1) << 2);
                Bf[ni] = *(const uint4*)(sm + SMB(st) + r * 128 + ch * 16);
            }

#pragma unroll
            for (int mi = 0; mi < 4; mi++)
#pragma unroll
                for (int ni = 0; ni < 8; ni++)
                    mma_bf16(acc[mi][ni], Af[mi][0].x, Af[mi][1].x, Af[mi][0].y, Af[mi][1].y,
                             Bf[ni].x, Bf[ni].y);
#pragma unroll
            for (int mi = 0; mi < 4; mi++)
#pragma unroll
                for (int ni = 0; ni < 8; ni++)
                    mma_bf16(acc[mi][ni], Af[mi][0].z, Af[mi][1].z, Af[mi][0].w, Af[mi][1].w,
                             Bf[ni].z, Bf[ni].w);
        }
    }

    // --- epilogue: write S as bf16, streaming (read-once downstream) ---
    __nv_bfloat16* Sp = g_S + (size_t)b * NSP * NSP;
#pragma unroll
    for (int mi = 0; mi < 4; mi++) {
        int r = n0 + warpM * 64 + mi * 16 + (l >> 2);
#pragma unroll
        for (int ni = 0; ni < 8; ni++) {
            int cg = m0 + warpN * 64 + ni * 8 + ((l & 3) << 1);
            __stcs((uint32_t*)(Sp + (size_t)r * NSP + cg),
                   pack_bf16x2(acc[mi][ni][0], acc[mi][ni][1]));
            __stcs((uint32_t*)(Sp + (size_t)(r + 8) * NSP + cg),
                   pack_bf16x2(acc[mi][ni][2], acc[mi][ni][3]));
        }
    }
}

// ------------------------- 4) per-row: smax -> sum_w -> maxA -----------------
// exp2-domain, folded constants, magic-number rounding, FFMA-only.
__global__ void k_reduce() {
    int row = blockIdx.x, tid = threadIdx.x;
    int l = tid & 31, w = tid >> 5;
    const uint4* p = (const uint4*)(g_S + (size_t)row * NSP);
    uint4 v0 = __ldcs(p + tid * 2), v1 = __ldcs(p + tid * 2 + 1);
    uint32_t u[8] = { v0.x, v0.y, v0.z, v0.w, v1.x, v1.y, v1.z, v1.w };
    float s[16];
    float mx = -1e30f;
#pragma unroll
    for (int j = 0; j < 8; j++) {
        s[2*j]   = __uint_as_float(u[j] << 16);
        s[2*j+1] = __uint_as_float(u[j] & 0xffff0000u);
        mx = fmaxf(mx, fmaxf(s[2*j], s[2*j+1]));
    }
    __shared__ float red[8];
    __shared__ float bcast;
#pragma unroll
    for (int off = 16; off > 0; off >>= 1)
        mx = fmaxf(mx, __shfl_xor_sync(0xffffffffu, mx, off));
    if (l == 0) red[w] = mx;
    __syncthreads();
    if (tid == 0) {
        float m = red[0];
#pragma unroll
        for (int i = 1; i < 8; i++) m = fmaxf(m, red[i]);
        bcast = m;
    }
    __syncthreads();
    float smax = bcast;
    // weight = exp((s - smax + 0.001) * 10/c) = 2^(s*kk2 + c2)
    float kk2 = 14.4269504089f / (1.001f - smax);          // 10*log2(e)/c
    float c2 = (0.001f - smax) * kk2;
    const float MAGIC = 12582912.0f;                       // 1.5 * 2^23
    float sum = 0.0f;
#pragma unroll
    for (int j = 0; j < 16; j++) {
        float y = fmaxf(fmaf(s[j], kk2, c2), -126.0f);
        float z = y + MAGIC;                               // RN -> integer part
        float t = y - (z - MAGIC);                         // frac in [-0.5, 0.5]
        float q = fmaf(t, 9.618129e-3f, 5.550411e-2f);     // 2^t Taylor deg-4
        q = fmaf(t, q, 2.402265e-1f);
        q = fmaf(t, q, 6.931472e-1f);
        q = fmaf(t, q, 1.0f);
        float sc = __int_as_float((__float_as_int(z) << 23) + 0x3F800000);
        sum = fmaf(q, sc, sum);
    }
#pragma unroll
    for (int off = 16; off > 0; off >>= 1)
        sum += __shfl_xor_sync(0xffffffffu, sum, off);
    if (l == 0) red[w] = sum;
    __syncthreads();
    if (tid == 0) {
        float tsum = 0.0f;
#pragma unroll
        for (int i = 0; i < 8; i++) tsum += red[i];
        g_maxA[row] = exp2f(0.001f * kk2) / tsum;
    }
}

// ------------------------- 5) loss -------------------------------------------
__global__ void k_final(float* __restrict__ out) {
    int b = blockIdx.x, tid = threadIdx.x;
    float s = 0.0f;
#pragma unroll
    for (int j = 0; j < 16; j++) s += g_maxA[b * NSP + tid + j * 256];
    __shared__ float red[256];
    red[tid] = s; __syncthreads();
    for (int off = 128; off > 0; off >>= 1) {
        if (tid < off) red[tid] += red[tid + off];
        __syncthreads();
    }
    if (tid == 0) out[b] = -logf(red[0] * (1.0f / NSP));
}

// ------------------------- launch --------------------------------------------
extern "C" void kernel_launch(void* const* d_in, const int* in_sizes, int n_in,
                              void* d_out, int out_size) {
    const float* X = (const float*)d_in[0];
    const float* Y = (const float*)d_in[1];
    float* out = (float*)d_out;

    cudaFuncSetAttribute(k_prep, cudaFuncAttributeMaxDynamicSharedMemorySize, PREP_SMEM);
    cudaFuncSetAttribute(k_gemm_mma, cudaFuncAttributeMaxDynamicSharedMemorySize, SM_TOT);

    k_mean<<<BB * CC, 256>>>(Y);
    k_prep<<<dim3(NSP / 32, BB), 256, PREP_SMEM>>>(X, Y);
    k_gemm_mma<<<dim3(NSP / 128, NSP / 128, BB), 128, SM_TOT>>>();
    k_reduce<<<BB * NSP, 256>>>();
    k_final<<<BB, 256>>>(out);
}